// round 3
// baseline (speedup 1.0000x reference)
#include <cuda_runtime.h>
#include <cstdint>

// ---------------- problem constants ----------------
#define T_TOK   32768            // B*S tokens
#define NXD     1024             // feature dim
#define A_CNT   20               // adapters
#define H_CNT   50               // hidden
#define O_CNT   3                // outputs per adapter
#define NC      1000             // A_CNT*H_CNT flat columns
#define S_LEN   2048
#define LN_EPS  1e-5f

// ---------------- device scratch (sanctioned __device__ globals) ----------------
__device__ float g_mu[T_TOK];
__device__ float g_rstd[T_TOK];
__device__ float g_off[NC];
__device__ float g_hbuf[(size_t)T_TOK * NC];   // 131 MB relu(xn@W1g + off)

// =====================================================================
// K1: per-token LayerNorm statistics (mean, rstd). One block per token.
// =====================================================================
__global__ void __launch_bounds__(256) k_lnstats(const float* __restrict__ x) {
    const int t = blockIdx.x;
    const float4* xv = reinterpret_cast<const float4*>(x) + (size_t)t * 256;
    float4 v = xv[threadIdx.x];
    float s  = v.x + v.y + v.z + v.w;
    float q  = v.x * v.x + v.y * v.y + v.z * v.z + v.w * v.w;
    #pragma unroll
    for (int o = 16; o > 0; o >>= 1) {
        s += __shfl_xor_sync(0xffffffffu, s, o);
        q += __shfl_xor_sync(0xffffffffu, q, o);
    }
    __shared__ float ss[8], qq[8];
    const int w = threadIdx.x >> 5;
    if ((threadIdx.x & 31) == 0) { ss[w] = s; qq[w] = q; }
    __syncthreads();
    if (threadIdx.x == 0) {
        float S = 0.f, Q = 0.f;
        #pragma unroll
        for (int i = 0; i < 8; i++) { S += ss[i]; Q += qq[i]; }
        float mu  = S * (1.0f / (float)NXD);
        float var = Q * (1.0f / (float)NXD) - mu * mu;
        var = fmaxf(var, 0.0f);
        g_mu[t]   = mu;
        g_rstd[t] = 1.0f / sqrtf(var + LN_EPS);
    }
}

// =====================================================================
// K2: off[a,h] = sum_n ln_b[a,n]*W1[a,n,h] + b1[a,h]   (beta folding)
// grid = A_CNT blocks of 64 threads (50 active)
// =====================================================================
__global__ void __launch_bounds__(64) k_off(const float* __restrict__ ln_b,
                                            const float* __restrict__ W1,
                                            const float* __restrict__ b1) {
    const int a = blockIdx.x;
    const int h = threadIdx.x;
    if (h >= H_CNT) return;
    const float* lb = ln_b + a * NXD;
    const float* w  = W1 + (size_t)a * NXD * H_CNT + h;
    float acc = 0.0f;
    #pragma unroll 8
    for (int n = 0; n < NXD; n++) acc += lb[n] * w[(size_t)n * H_CNT];
    g_off[a * H_CNT + h] = acc + b1[a * H_CNT + h];
}

// =====================================================================
// K3: main GEMM  H = relu( xn @ (ln_g ⊙ W1) + off )
//   M = 32768 tokens, N = 1024 (cols 1000..1023 wasted), K = 1024
//   BM=128, BN=128, BK=8; 256 threads; micro-tile 8(M) x 8(N)
//   Accumulators are f32x2 pairs along N; A is stored DUPLICATED {a,a}
//   in smem so the inner loop is pure fma.rn.f32x2 (FFMA2).
//   LN normalization folded into A load; gamma folded into B load.
// =====================================================================
__global__ void __launch_bounds__(256, 2) k_gemm(const float* __restrict__ x,
                                                 const float* __restrict__ ln_g,
                                                 const float* __restrict__ W1) {
    __shared__ float2 As[8][128];   // duplicated A: As[k][m] = {a,a}
    __shared__ float  Bs[8][128];

    const int tid = threadIdx.x;
    const int tx  = tid & 15;       // N direction (8 cols each)
    const int ty  = tid >> 4;       // M direction (8 rows each)
    const int nt  = blockIdx.x;     // 0..7
    const int mt  = blockIdx.y;     // 0..255

    // ---- A-tile load mapping: thread owns one token row, half the k-chunk
    const int am  = tid >> 1;       // 0..127 row within tile
    const int ak4 = tid & 1;        // which float4 of the 8-wide k chunk
    const int tok = mt * 128 + am;
    const float mu = g_mu[tok];
    const float rs = g_rstd[tok];
    const float4* xrow = reinterpret_cast<const float4*>(x) + (size_t)tok * 256;

    // ---- B-tile load mapping: 8 k-rows x 128 cols, 4 cols per thread
    const int bk = tid >> 5;            // 0..7
    const int bc = (tid & 31) * 4;      // 0..124
    int  aidx[4], wbase[4];
    bool cval[4];
    #pragma unroll
    for (int q = 0; q < 4; q++) {
        int ci = nt * 128 + bc + q;
        cval[q] = (ci < NC);
        int a = ci / H_CNT;
        if (!cval[q]) a = 0;            // keep speculative loads in-bounds
        int h = ci - a * H_CNT;
        aidx[q]  = a;
        wbase[q] = a * (NXD * H_CNT) + h;
    }

    unsigned long long acc[8][4];
    #pragma unroll
    for (int m = 0; m < 8; m++)
        #pragma unroll
        for (int p = 0; p < 4; p++) acc[m][p] = 0ull;

    // ---- prologue: prefetch tile kt=0 into registers
    float4 areg = xrow[ak4];
    float  breg[4];
    {
        const int n = bk;
        #pragma unroll
        for (int q = 0; q < 4; q++)
            breg[q] = cval[q] ? ln_g[aidx[q] * NXD + n] * W1[wbase[q] + n * H_CNT] : 0.0f;
    }

    for (int kt = 0; kt < 128; kt++) {
        // commit prefetched tile to smem (normalize A, duplicate it)
        {
            float vv[4] = {areg.x, areg.y, areg.z, areg.w};
            #pragma unroll
            for (int i = 0; i < 4; i++) {
                float nv = (vv[i] - mu) * rs;
                As[ak4 * 4 + i][am] = make_float2(nv, nv);
            }
            *reinterpret_cast<float4*>(&Bs[bk][bc]) =
                make_float4(breg[0], breg[1], breg[2], breg[3]);
        }
        __syncthreads();

        // prefetch next tile while computing current one
        if (kt < 127) {
            areg = xrow[(kt + 1) * 2 + ak4];
            const int n = (kt + 1) * 8 + bk;
            #pragma unroll
            for (int q = 0; q < 4; q++)
                breg[q] = cval[q] ? ln_g[aidx[q] * NXD + n] * W1[wbase[q] + n * H_CNT] : 0.0f;
        }

        // ---- inner product: 8 k-steps, 8x4 FFMA2 each (= 64 FMA/thread/k)
        #pragma unroll
        for (int k = 0; k < 8; k++) {
            unsigned long long a_[8], b_[4];
            const ulonglong2* ap = reinterpret_cast<const ulonglong2*>(&As[k][ty * 8]);
            ulonglong2 t0 = ap[0], t1 = ap[1], t2 = ap[2], t3 = ap[3];
            a_[0] = t0.x; a_[1] = t0.y; a_[2] = t1.x; a_[3] = t1.y;
            a_[4] = t2.x; a_[5] = t2.y; a_[6] = t3.x; a_[7] = t3.y;
            const ulonglong2* bp = reinterpret_cast<const ulonglong2*>(&Bs[k][tx * 8]);
            ulonglong2 u0 = bp[0], u1 = bp[1];
            b_[0] = u0.x; b_[1] = u0.y; b_[2] = u1.x; b_[3] = u1.y;
            #pragma unroll
            for (int m = 0; m < 8; m++)
                #pragma unroll
                for (int p = 0; p < 4; p++)
                    asm("fma.rn.f32x2 %0, %1, %2, %0;"
                        : "+l"(acc[m][p]) : "l"(a_[m]), "l"(b_[p]));
        }
        __syncthreads();
    }

    // ---- epilogue: +off, relu, store to g_hbuf (row length NC=1000)
    #pragma unroll
    for (int m = 0; m < 8; m++) {
        const int row = mt * 128 + ty * 8 + m;
        float* hb = g_hbuf + (size_t)row * NC;
        #pragma unroll
        for (int p = 0; p < 4; p++) {
            const int c0 = nt * 128 + tx * 8 + p * 2;
            float lo = __uint_as_float((unsigned)(acc[m][p] & 0xffffffffull));
            float hi = __uint_as_float((unsigned)(acc[m][p] >> 32));
            if (c0 < NC)     hb[c0]     = fmaxf(lo + g_off[c0], 0.0f);
            if (c0 + 1 < NC) hb[c0 + 1] = fmaxf(hi + g_off[c0 + 1], 0.0f);
        }
    }
}

// =====================================================================
// K4: per-token second GEMM (50->3 per adapter) + cross-adapter squash
//   o[a,j] = h·W2[a,:,j] + b2 ;  sq[j] = sum_a o^2 ; out = o*sqrt(sq)/(1+sq)
//   One warp per token, 8 tokens per block.
// =====================================================================
__global__ void __launch_bounds__(256) k_out(const float* __restrict__ W2,
                                             const float* __restrict__ b2,
                                             float* __restrict__ out) {
    __shared__ float W2s[A_CNT * H_CNT * O_CNT];  // 3000
    __shared__ float b2s[A_CNT * O_CNT];          // 60
    __shared__ float hrow[8][NC];
    __shared__ float osm[8][64];
    __shared__ float scl[8][4];

    const int tid = threadIdx.x;
    for (int i = tid; i < A_CNT * H_CNT * O_CNT; i += 256) W2s[i] = W2[i];
    if (tid < A_CNT * O_CNT) b2s[tid] = b2[tid];
    __syncthreads();

    const int w = tid >> 5, l = tid & 31;
    const int t = blockIdx.x * 8 + w;
    const float* hb = g_hbuf + (size_t)t * NC;
    #pragma unroll
    for (int i = 0; i < 32; i++) {
        int idx = i * 32 + l;
        if (idx < NC) hrow[w][idx] = hb[idx];
    }
    __syncwarp();

    #pragma unroll
    for (int r = 0; r < 2; r++) {
        const int p = l + r * 32;
        if (p < A_CNT * O_CNT) {
            const int a = p / 3, j = p - a * 3;
            const float* hr = &hrow[w][a * H_CNT];
            const float* w2 = &W2s[a * H_CNT * O_CNT + j];
            float o = b2s[p];
            #pragma unroll
            for (int h = 0; h < H_CNT; h++) o += hr[h] * w2[h * 3];
            osm[w][p] = o;
        }
    }
    __syncwarp();

    if (l < O_CNT) {
        float sq = 0.0f;
        #pragma unroll
        for (int a = 0; a < A_CNT; a++) { float v = osm[w][a * 3 + l]; sq += v * v; }
        scl[w][l] = sqrtf(sq) / (1.0f + sq);   // == (sq/(1+sq)) * rsqrt(sq)
    }
    __syncwarp();

    const int b = t >> 11, sidx = t & (S_LEN - 1);
    #pragma unroll
    for (int r = 0; r < 2; r++) {
        const int p = l + r * 32;
        if (p < A_CNT * O_CNT) {
            const int a = p / 3, j = p - a * 3;
            out[(size_t)(b * A_CNT + a) * (S_LEN * O_CNT) + sidx * 3 + j] =
                osm[w][p] * scl[w][j];
        }
    }
}

// =====================================================================
// launch
// =====================================================================
extern "C" void kernel_launch(void* const* d_in, const int* in_sizes, int n_in,
                              void* d_out, int out_size) {
    (void)in_sizes; (void)n_in; (void)out_size;
    const float* x    = (const float*)d_in[0];
    const float* ln_g = (const float*)d_in[1];
    const float* ln_b = (const float*)d_in[2];
    const float* W1   = (const float*)d_in[3];
    const float* b1   = (const float*)d_in[4];
    const float* W2   = (const float*)d_in[5];
    const float* b2   = (const float*)d_in[6];
    float* out = (float*)d_out;

    k_lnstats<<<T_TOK, 256>>>(x);
    k_off<<<A_CNT, 64>>>(ln_b, W1, b1);
    k_gemm<<<dim3(8, 256), 256>>>(x, ln_g, W1);
    k_out<<<T_TOK / 8, 256>>>(W2, b2, out);
}